// round 8
// baseline (speedup 1.0000x reference)
#include <cuda_runtime.h>

#define R_TOT 2048
#define A_TOT 16384
#define E_TOT 131072
#define KNBR  48
#define NBINS 2304          // d-bits >> 19 (exp + 4 mantissa bits); 256 thr x 9
#define CAND_CAP 1024

// ---------------- scratch (single __device__ blob, offsets in floats) ------
constexpr int OFF_XCAT1 = 0;
constexpr int OFF_WCAT  = OFF_XCAT1 + R_TOT * 512;   // 1048576
constexpr int OFF_EMBW  = OFF_WCAT  + 512 * 512;     // 1310720
constexpr int OFF_M1    = OFF_EMBW  + 39 * 128;      // 1315712
constexpr int OFF_ENV   = OFF_M1    + 384;           // 1316096
constexpr int OFF_XCAT2 = OFF_ENV   + R_TOT * 128;   // 1578240
constexpr int OFF_Z     = OFF_XCAT2 + R_TOT * 768;   // 3151104
constexpr int OFF_SCALE = OFF_Z     + R_TOT * 512;   // 4199680
constexpr int OFF_SHIFT = OFF_SCALE + 512;
constexpr int OFF_POSX  = OFF_SHIFT + 512;           // SoA positions
constexpr int OFF_POSY  = OFF_POSX + A_TOT;
constexpr int OFF_POSZ  = OFF_POSY + A_TOT;
constexpr int SCRATCH_N = OFF_POSZ + A_TOT;

__device__ __align__(16) float g_scratch[SCRATCH_N];

// ---- packed fp32x2 helpers (Blackwell FFMA2 path; ptxas won't auto-fuse) --
#define FMA_F32X2(d, a, b, c) \
    asm("fma.rn.f32x2 %0, %1, %2, %3;" : "=l"(d) : "l"(a), "l"(b), "l"(c))
__device__ __forceinline__ unsigned long long pack_bcast(float v) {
    unsigned long long r;
    asm("mov.b64 %0, {%1, %1};" : "=l"(r) : "f"(v));
    return r;
}
__device__ __forceinline__ void unpack2(unsigned long long v, float& lo, float& hi) {
    asm("mov.b64 {%0, %1}, %2;" : "=f"(lo), "=f"(hi) : "l"(v));
}

// ---------------- setup: Wcat copy, embW1b, M1, pos AoS->SoA ---------------
__global__ void k_prep(float* __restrict__ Wcat, float* __restrict__ embw,
                       float* __restrict__ m1, float* __restrict__ posx,
                       float* __restrict__ posy, float* __restrict__ posz,
                       const float* __restrict__ Wconv, const float* __restrict__ Wself,
                       const float* __restrict__ emb, const float* __restrict__ W1,
                       const float* __restrict__ b1, const float* __restrict__ Wxyz,
                       const float* __restrict__ pos) {
    int i = blockIdx.x * 256 + threadIdx.x;
    if (i < 262144) {
        int r = i >> 9;
        Wcat[i] = (r < 448) ? Wconv[i] : Wself[i - 448 * 512];
    } else if (i < 262144 + 4992) {
        int j = i - 262144;
        int e = j >> 7, d = j & 127;
        float acc = b1[d];
        for (int k = 0; k < 64; k++) acc = fmaf(emb[e * 64 + k], W1[k * 128 + d], acc);
        embw[j] = acc;
    } else if (i < 267520) {
        int j = i - 267136;
        int rr = j >> 7, d = j & 127;
        float acc = 0.f;
        for (int k = 0; k < 64; k++) acc = fmaf(Wxyz[rr * 64 + k], W1[k * 128 + d], acc);
        m1[j] = acc;
    } else if (i < 267520 + A_TOT) {
        int j = i - 267520;
        posx[j] = pos[3 * j];
        posy[j] = pos[3 * j + 1];
        posz[j] = pos[3 * j + 2];
    }
}

// ---------------- res_feat into Xcat1 tail + zero agg region ---------------
__global__ void k_resfeat(float* __restrict__ Xcat1, const float* __restrict__ nf,
                          const float* __restrict__ Wres, const float* __restrict__ bres) {
    int i = blockIdx.x * 256 + threadIdx.x;
    int r = i >> 9, c = i & 511;
    if (c < 448) { Xcat1[i] = 0.f; return; }
    int f = c - 448;
    float acc = bres[f];
    for (int k = 0; k < 21; k++) acc = fmaf(nf[r * 21 + k], Wres[k * 64 + f], acc);
    Xcat1[i] = acc;
}

// ---------------- relational scatter-sum (warp per edge) ------------------
__global__ void k_scatter(float* __restrict__ Xcat1, const int* __restrict__ esrc,
                          const int* __restrict__ edst, const int* __restrict__ erel) {
    int e = blockIdx.x * 8 + (threadIdx.x >> 5);
    int lane = threadIdx.x & 31;
    int s = esrc[e], d = edst[e], rl = erel[e];
    const float* rf = Xcat1 + s * 512 + 448;
    float* out = Xcat1 + d * 512 + rl * 64;
    atomicAdd(out + lane,      rf[lane]);
    atomicAdd(out + lane + 32, rf[lane + 32]);
}

// ---------------- ball query + point MLP + max-pool ------------------------
// Ordering key = ROUNDED d = sqrt_rn(d2 + 1e-12) (bit pattern), ties by idx:
// exactly reproduces the reference's top_k over rounded distances, including
// rounding collisions. Membership = the literal reference predicate d < 10.
struct BallSM {
    unsigned long long cand[CAND_CAP];
    unsigned long long red[16];
    float dist[A_TOT];          // rounded d per atom
    int   hist[NBINS];
    int   coarse[256];
    float embw[39 * 128];
    float m1[384];
    float env2[2][128];
    float sdx[64], sdy[64], sdz[64];
    int   snm[64], sidx[64];
    float ca[3];
    int   cnt_sel, cnt_cand, selN, binB, needN;
};

__global__ void __launch_bounds__(256) k_ball(
    float* __restrict__ envout, const float* __restrict__ pos,
    const float* __restrict__ posx, const float* __restrict__ posy,
    const float* __restrict__ posz,
    const int* __restrict__ aname, const int* __restrict__ ca_idx,
    const float* __restrict__ embw_g, const float* __restrict__ m1_g) {
    extern __shared__ char smraw[];
    BallSM* s = (BallSM*)smraw;
    int tid = threadIdx.x;
    int r = blockIdx.x;

    for (int i = tid; i < NBINS; i += 256) s->hist[i] = 0;
    for (int i = tid; i < 39 * 128; i += 256) s->embw[i] = embw_g[i];
    for (int i = tid; i < 384; i += 256) s->m1[i] = m1_g[i];
    if (tid == 0) {
        s->cnt_sel = 0; s->cnt_cand = 0;
        int ci = ca_idx[r];
        s->ca[0] = pos[3 * ci]; s->ca[1] = pos[3 * ci + 1]; s->ca[2] = pos[3 * ci + 2];
    }
    __syncthreads();
    float cax = s->ca[0], cay = s->ca[1], caz = s->ca[2];

    // pass 1: rounded d (reference rounding exactly) + float-radix histogram
    for (int i = tid; i < A_TOT; i += 256) {
        float dx = __fsub_rn(cax, posx[i]);
        float dy = __fsub_rn(cay, posy[i]);
        float dz = __fsub_rn(caz, posz[i]);
        float d2 = __fadd_rn(__fadd_rn(__fmul_rn(dx, dx), __fmul_rn(dy, dy)),
                             __fmul_rn(dz, dz));
        float d = __fsqrt_rn(__fadd_rn(d2, 1e-12f));
        s->dist[i] = d;
        if (d < 10.0f) atomicAdd(&s->hist[__float_as_uint(d) >> 19], 1);
    }
    __syncthreads();

    { // coarse partial sums (9 bins per thread; 256*9 = 2304 = NBINS)
        int acc = 0, b0 = tid * 9;
        #pragma unroll
        for (int j = 0; j < 9; j++) acc += s->hist[b0 + j];
        s->coarse[tid] = acc;
    }
    __syncthreads();

    if (tid == 0) {
        int T = 0;
        for (int i = 0; i < 256; i++) T += s->coarse[i];
        int sel = T < KNBR ? T : KNBR;
        s->selN = sel;
        if (sel == 0) { s->binB = -1; s->needN = 0; }
        else {
            int cum = 0, cb = 0;
            while (cum + s->coarse[cb] < sel) { cum += s->coarse[cb]; cb++; }
            int b = cb * 9;
            while (cum + s->hist[b] < sel) { cum += s->hist[b]; b++; }
            s->binB = b;
            s->needN = sel - cum;
        }
    }
    __syncthreads();
    int B = s->binB;

    // pass 2: accept keys < boundary bin, collect boundary-bin candidates
    for (int i = tid; i < A_TOT; i += 256) {
        float d = s->dist[i];
        if (d < 10.0f) {
            int k = (int)(__float_as_uint(d) >> 19);
            if (k < B) {
                int p = atomicAdd(&s->cnt_sel, 1);
                s->sidx[p] = i;
            } else if (k == B) {
                int p = atomicAdd(&s->cnt_cand, 1);
                if (p < CAND_CAP)
                    s->cand[p] = ((unsigned long long)__float_as_uint(d) << 32) | (unsigned)i;
            }
        }
    }
    __syncthreads();

    // exact selection of `need` smallest from boundary bin
    // key = (d_bits, idx): equal rounded d -> lower idx first (top_k stable)
    int need = s->needN;
    int cbase = s->cnt_sel;
    int nc = s->cnt_cand; if (nc > CAND_CAP) nc = CAND_CAP;
    for (int it = 0; it < need; it++) {
        unsigned long long mn = ~0ull;
        for (int j = tid; j < nc; j += 256) {
            unsigned long long v = s->cand[j];
            if (v < mn) mn = v;
        }
        #pragma unroll
        for (int o = 16; o; o >>= 1) {
            unsigned long long w = __shfl_xor_sync(0xffffffffu, mn, o);
            if (w < mn) mn = w;
        }
        if ((tid & 31) == 0) s->red[tid >> 5] = mn;
        __syncthreads();
        if (tid == 0) {
            unsigned long long m = ~0ull;
            for (int w = 0; w < 8; w++) if (s->red[w] < m) m = s->red[w];
            s->red[8] = m;
            int idx = (m == ~0ull) ? s->sidx[0] : (int)(m & 0xffffffffu);
            s->sidx[cbase + it] = idx;
        }
        __syncthreads();
        unsigned long long win = s->red[8];
        for (int j = tid; j < nc; j += 256)
            if (s->cand[j] == win) s->cand[j] = ~0ull;
        __syncthreads();
    }

    int sel = s->selN;
    if (tid < sel) {
        int i = s->sidx[tid];
        s->sdx[tid] = pos[3 * i] - cax;
        s->sdy[tid] = pos[3 * i + 1] - cay;
        s->sdz[tid] = pos[3 * i + 2] - caz;
        s->snm[tid] = aname[i];
    }
    __syncthreads();

    int g = tid >> 7, d = tid & 127;
    float acc = 0.f;
    for (int j = g; j < sel; j += 2) {
        float h = s->embw[s->snm[j] * 128 + d];
        h = fmaf(s->sdx[j], s->m1[d],       h);
        h = fmaf(s->sdy[j], s->m1[128 + d], h);
        h = fmaf(s->sdz[j], s->m1[256 + d], h);
        acc = fmaxf(acc, fmaxf(h, 0.f));
    }
    s->env2[g][d] = acc;
    __syncthreads();
    if (tid < 128) envout[r * 128 + tid] = fmaxf(s->env2[0][tid], s->env2[1][tid]);
}

// ---------------- packed-f32x2 tiled SGEMM, broadcast-B design -------------
// C = [relu](A' @ B + bias); A row-major [M,K], B row-major [K,N].
// BNA: A' = relu(A*scale + shift) applied at the A-tile fill.
// Tile 128x64, 256 threads (8 warps). Each warp = one 8-column group across
// ALL 128 rows; lane l owns row-pairs {2l,2l+1} and {64+2l,65+2l}.
// B values are warp-uniform -> broadcast LDS.128 (1 wavefront each), so the
// crossbar demand matches the FFMA2 issue time: fma-bound by construction.
template <bool RELU, bool BNA>
__global__ void __launch_bounds__(256) k_gemm2(
    const float* __restrict__ A, int lda, const float* __restrict__ B, int ldb,
    const float* __restrict__ bias, float* __restrict__ C, int ldc, int K,
    const float* __restrict__ bnscale, const float* __restrict__ bnshift) {
    __shared__ __align__(16) unsigned int As32[32][132];
    __shared__ __align__(16) unsigned long long Bs2[32][66];

    int m0 = blockIdx.y * 128, n0 = blockIdx.x * 64;
    int tid = threadIdx.x;
    int lane = tid & 31, cg = tid >> 5;     // cg: column group 0..7

    unsigned long long acc[2][8];
    #pragma unroll
    for (int p = 0; p < 2; p++)
        #pragma unroll
        for (int j = 0; j < 8; j++) acc[p][j] = 0ull;

    for (int k0 = 0; k0 < K; k0 += 32) {
        // ---- fill A tile transposed: As32[k][row] = A[m0+row][k0+k] -------
        #pragma unroll
        for (int l = tid; l < 1024; l += 256) {      // 128 rows x 8 float4
            int row = l >> 3, kq = (l & 7) * 4;
            float4 v = *(const float4*)(A + (m0 + row) * lda + k0 + kq);
            if (BNA) {
                float4 sc = *(const float4*)(bnscale + k0 + kq);
                float4 sh = *(const float4*)(bnshift + k0 + kq);
                v.x = fmaxf(fmaf(v.x, sc.x, sh.x), 0.f);
                v.y = fmaxf(fmaf(v.y, sc.y, sh.y), 0.f);
                v.z = fmaxf(fmaf(v.z, sc.z, sh.z), 0.f);
                v.w = fmaxf(fmaf(v.w, sc.w, sh.w), 0.f);
            }
            As32[kq][row]     = __float_as_uint(v.x);
            As32[kq + 1][row] = __float_as_uint(v.y);
            As32[kq + 2][row] = __float_as_uint(v.z);
            As32[kq + 3][row] = __float_as_uint(v.w);
        }
        // ---- fill B tile, pre-broadcast into {b,b} u64 pairs --------------
        #pragma unroll
        for (int l = tid; l < 512; l += 256) {       // 32 k x 16 float4
            int k = l >> 4, c4 = (l & 15) * 4;
            float4 v = *(const float4*)(B + (k0 + k) * ldb + n0 + c4);
            Bs2[k][c4]     = pack_bcast(v.x);
            Bs2[k][c4 + 1] = pack_bcast(v.y);
            Bs2[k][c4 + 2] = pack_bcast(v.z);
            Bs2[k][c4 + 3] = pack_bcast(v.w);
        }
        __syncthreads();
        #pragma unroll
        for (int k = 0; k < 32; k++) {
            const unsigned long long* ak = (const unsigned long long*)&As32[k][0];
            unsigned long long a0 = ak[lane];        // rows 2l, 2l+1
            unsigned long long a1 = ak[32 + lane];   // rows 64+2l, 65+2l
            const ulonglong2* bk = (const ulonglong2*)&Bs2[k][cg * 8];
            ulonglong2 b01 = bk[0], b23 = bk[1], b45 = bk[2], b67 = bk[3];
            unsigned long long b[8] = {b01.x, b01.y, b23.x, b23.y,
                                       b45.x, b45.y, b67.x, b67.y};
            #pragma unroll
            for (int j = 0; j < 8; j++) {
                FMA_F32X2(acc[0][j], a0, b[j], acc[0][j]);
                FMA_F32X2(acc[1][j], a1, b[j], acc[1][j]);
            }
        }
        __syncthreads();
    }

    // ---- epilogue: bias (+relu), write 4 rows x 8 cols per lane -----------
    float bb[8];
    *(float4*)&bb[0] = *(const float4*)(bias + n0 + cg * 8);
    *(float4*)&bb[4] = *(const float4*)(bias + n0 + cg * 8 + 4);
    #pragma unroll
    for (int p = 0; p < 2; p++) {
        float lo[8], hi[8];
        #pragma unroll
        for (int j = 0; j < 8; j++) {
            unpack2(acc[p][j], lo[j], hi[j]);
            lo[j] += bb[j]; hi[j] += bb[j];
            if (RELU) { lo[j] = fmaxf(lo[j], 0.f); hi[j] = fmaxf(hi[j], 0.f); }
        }
        int r0 = m0 + p * 64 + 2 * lane;
        float* c0 = C + r0 * ldc + n0 + cg * 8;
        float* c1 = c0 + ldc;
        *(float4*)c0       = *(float4*)&lo[0];
        *(float4*)(c0 + 4) = *(float4*)&lo[4];
        *(float4*)c1       = *(float4*)&hi[0];
        *(float4*)(c1 + 4) = *(float4*)&hi[4];
    }
}

// ---------------- BN stats -> folded scale/shift ---------------------------
__global__ void k_bnstats(const float* __restrict__ z, const float* __restrict__ gamma,
                          const float* __restrict__ beta, float* __restrict__ scale,
                          float* __restrict__ shift) {
    __shared__ float S[8][32], S2[8][32];
    int cx = threadIdx.x & 31, ry = threadIdx.x >> 5;
    int c = blockIdx.x * 32 + cx;
    float su = 0.f, sq = 0.f;
    for (int r = ry; r < R_TOT; r += 8) {
        float v = z[r * 512 + c];
        su += v; sq = fmaf(v, v, sq);
    }
    S[ry][cx] = su; S2[ry][cx] = sq;
    __syncthreads();
    if (threadIdx.x < 32) {
        int cc = blockIdx.x * 32 + threadIdx.x;
        float t = 0.f, t2 = 0.f;
        for (int i = 0; i < 8; i++) { t += S[i][threadIdx.x]; t2 += S2[i][threadIdx.x]; }
        float mean = t * (1.f / R_TOT);
        float var = t2 * (1.f / R_TOT) - mean * mean;
        float sc = gamma[cc] * rsqrtf(var + 1e-5f);
        scale[cc] = sc;
        shift[cc] = beta[cc] - mean * sc;
    }
}

// ---------------- launch ---------------------------------------------------
extern "C" void kernel_launch(void* const* d_in, const int* in_sizes, int n_in,
                              void* d_out, int out_size) {
    const float* node_feature = (const float*)d_in[0];
    const float* atom_pos     = (const float*)d_in[1];
    const int*   atom_name    = (const int*)d_in[2];
    const int*   ca_idx       = (const int*)d_in[3];
    const int*   edge_src     = (const int*)d_in[4];
    const int*   edge_dst     = (const int*)d_in[5];
    const int*   edge_rel     = (const int*)d_in[6];
    const float* emb_atom     = (const float*)d_in[7];
    const float* Wres         = (const float*)d_in[8];
    const float* bres         = (const float*)d_in[9];
    const float* Wxyz         = (const float*)d_in[10];
    const float* W1           = (const float*)d_in[11];
    const float* b1           = (const float*)d_in[12];
    const float* W2           = (const float*)d_in[13];
    const float* b2           = (const float*)d_in[14];
    const float* Wconv        = (const float*)d_in[15];
    const float* bconv        = (const float*)d_in[16];
    const float* Wself        = (const float*)d_in[17];
    const float* We1          = (const float*)d_in[18];
    const float* be1          = (const float*)d_in[19];
    const float* gamma1       = (const float*)d_in[20];
    const float* beta1        = (const float*)d_in[21];
    const float* We2          = (const float*)d_in[22];
    const float* be2          = (const float*)d_in[23];
    float* out = (float*)d_out;

    float* base = nullptr;
    cudaGetSymbolAddress((void**)&base, g_scratch);
    float* Xcat1 = base + OFF_XCAT1;
    float* Wcat  = base + OFF_WCAT;
    float* embw  = base + OFF_EMBW;
    float* m1    = base + OFF_M1;
    float* env   = base + OFF_ENV;
    float* Xcat2 = base + OFF_XCAT2;
    float* z     = base + OFF_Z;
    float* scale = base + OFF_SCALE;
    float* shift = base + OFF_SHIFT;
    float* posx  = base + OFF_POSX;
    float* posy  = base + OFF_POSY;
    float* posz  = base + OFF_POSZ;

    // setup (includes pos AoS->SoA transpose)
    k_prep<<<(267520 + A_TOT + 255) / 256, 256>>>(Wcat, embw, m1, posx, posy, posz,
                                                  Wconv, Wself, emb_atom, W1, b1, Wxyz,
                                                  atom_pos);
    k_resfeat<<<(R_TOT * 512) / 256, 256>>>(Xcat1, node_feature, Wres, bres);

    // relational scatter-sum
    k_scatter<<<E_TOT / 8, 256>>>(Xcat1, edge_src, edge_dst, edge_rel);

    // ball query + point MLP + maxpool
    cudaFuncSetAttribute(k_ball, cudaFuncAttributeMaxDynamicSharedMemorySize,
                         (int)sizeof(BallSM));
    k_ball<<<R_TOT, 256, sizeof(BallSM)>>>(env, atom_pos, posx, posy, posz,
                                           atom_name, ca_idx, embw, m1);

    // env256 = relu(env128 @ W2 + b2) -> Xcat2[:,512:768]
    {
        dim3 grid(256 / 64, R_TOT / 128);
        k_gemm2<true, false><<<grid, 256>>>(env, 128, W2, 256, b2, Xcat2 + 512, 768, 128,
                                            nullptr, nullptr);
    }
    // hres = relu(Xcat1 @ Wcat + bconv) -> Xcat2[:,0:512]
    {
        dim3 grid(512 / 64, R_TOT / 128);
        k_gemm2<true, false><<<grid, 256>>>(Xcat1, 512, Wcat, 512, bconv, Xcat2, 768, 512,
                                            nullptr, nullptr);
    }
    // z = Xcat2 @ We1 + be1
    {
        dim3 grid(512 / 64, R_TOT / 128);
        k_gemm2<false, false><<<grid, 256>>>(Xcat2, 768, We1, 512, be1, z, 512, 768,
                                             nullptr, nullptr);
    }
    // BN stats -> folded affine
    k_bnstats<<<512 / 32, 256>>>(z, gamma1, beta1, scale, shift);
    // out = relu(BN(z)) @ We2 + be2
    {
        dim3 grid(512 / 64, R_TOT / 128);
        k_gemm2<false, true><<<grid, 256>>>(z, 512, We2, 512, be2, out, 512, 512,
                                            scale, shift);
    }
}

// round 9
// speedup vs baseline: 1.3518x; 1.3518x over previous
#include <cuda_runtime.h>

#define R_TOT 2048
#define A_TOT 16384
#define E_TOT 131072
#define KNBR  48
#define NBINS 2304          // d-bits >> 19 (exp + 4 mantissa bits); 256 thr x 9
#define CAND_CAP 1024

// ---------------- scratch (single __device__ blob, offsets in floats) ------
constexpr int OFF_XCAT1 = 0;
constexpr int OFF_WCAT  = OFF_XCAT1 + R_TOT * 512;   // 1048576
constexpr int OFF_EMBW  = OFF_WCAT  + 512 * 512;     // 1310720
constexpr int OFF_M1    = OFF_EMBW  + 39 * 128;      // 1315712
constexpr int OFF_ENV   = OFF_M1    + 384;           // 1316096
constexpr int OFF_XCAT2 = OFF_ENV   + R_TOT * 128;   // 1578240
constexpr int OFF_Z     = OFF_XCAT2 + R_TOT * 768;   // 3151104
constexpr int OFF_SCALE = OFF_Z     + R_TOT * 512;   // 4199680
constexpr int OFF_SHIFT = OFF_SCALE + 512;
constexpr int OFF_POSX  = OFF_SHIFT + 512;           // SoA positions
constexpr int OFF_POSY  = OFF_POSX + A_TOT;
constexpr int OFF_POSZ  = OFF_POSY + A_TOT;
constexpr int SCRATCH_N = OFF_POSZ + A_TOT;

__device__ __align__(16) float g_scratch[SCRATCH_N];

// ---- packed fp32x2 helpers (Blackwell FFMA2 path; ptxas won't auto-fuse) --
#define FMA_F32X2(d, a, b, c) \
    asm("fma.rn.f32x2 %0, %1, %2, %3;" : "=l"(d) : "l"(a), "l"(b), "l"(c))
__device__ __forceinline__ unsigned long long pack_bcast(float v) {
    unsigned long long r;
    asm("mov.b64 %0, {%1, %1};" : "=l"(r) : "f"(v));
    return r;
}
__device__ __forceinline__ void unpack2(unsigned long long v, float& lo, float& hi) {
    asm("mov.b64 {%0, %1}, %2;" : "=f"(lo), "=f"(hi) : "l"(v));
}

// ---------------- setup: Wcat copy, embW1b, M1, pos AoS->SoA ---------------
__global__ void k_prep(float* __restrict__ Wcat, float* __restrict__ embw,
                       float* __restrict__ m1, float* __restrict__ posx,
                       float* __restrict__ posy, float* __restrict__ posz,
                       const float* __restrict__ Wconv, const float* __restrict__ Wself,
                       const float* __restrict__ emb, const float* __restrict__ W1,
                       const float* __restrict__ b1, const float* __restrict__ Wxyz,
                       const float* __restrict__ pos) {
    int i = blockIdx.x * 256 + threadIdx.x;
    if (i < 262144) {
        int r = i >> 9;
        Wcat[i] = (r < 448) ? Wconv[i] : Wself[i - 448 * 512];
    } else if (i < 262144 + 4992) {
        int j = i - 262144;
        int e = j >> 7, d = j & 127;
        float acc = b1[d];
        for (int k = 0; k < 64; k++) acc = fmaf(emb[e * 64 + k], W1[k * 128 + d], acc);
        embw[j] = acc;
    } else if (i < 267520) {
        int j = i - 267136;
        int rr = j >> 7, d = j & 127;
        float acc = 0.f;
        for (int k = 0; k < 64; k++) acc = fmaf(Wxyz[rr * 64 + k], W1[k * 128 + d], acc);
        m1[j] = acc;
    } else if (i < 267520 + A_TOT) {
        int j = i - 267520;
        posx[j] = pos[3 * j];
        posy[j] = pos[3 * j + 1];
        posz[j] = pos[3 * j + 2];
    }
}

// ---------------- res_feat into Xcat1 tail + zero agg region ---------------
__global__ void k_resfeat(float* __restrict__ Xcat1, const float* __restrict__ nf,
                          const float* __restrict__ Wres, const float* __restrict__ bres) {
    int i = blockIdx.x * 256 + threadIdx.x;
    int r = i >> 9, c = i & 511;
    if (c < 448) { Xcat1[i] = 0.f; return; }
    int f = c - 448;
    float acc = bres[f];
    for (int k = 0; k < 21; k++) acc = fmaf(nf[r * 21 + k], Wres[k * 64 + f], acc);
    Xcat1[i] = acc;
}

// ---------------- relational scatter-sum (warp per edge) ------------------
__global__ void k_scatter(float* __restrict__ Xcat1, const int* __restrict__ esrc,
                          const int* __restrict__ edst, const int* __restrict__ erel) {
    int e = blockIdx.x * 8 + (threadIdx.x >> 5);
    int lane = threadIdx.x & 31;
    int s = esrc[e], d = edst[e], rl = erel[e];
    const float* rf = Xcat1 + s * 512 + 448;
    float* out = Xcat1 + d * 512 + rl * 64;
    atomicAdd(out + lane,      rf[lane]);
    atomicAdd(out + lane + 32, rf[lane + 32]);
}

// ---------------- ball query + point MLP + max-pool ------------------------
// Ordering key = ROUNDED d = sqrt_rn(d2 + 1e-12) (bit pattern), ties by idx:
// reproduces the reference's top_k over rounded d exactly.
// Low-smem design (~22 KB static): NO per-atom dist array (d recomputed in
// pass 2 with the identical instruction sequence -> identical bits), embw
// read from global (L2-hot). 8 blocks/SM vs 2 before.
struct BallSM {
    unsigned long long cand[CAND_CAP];   // 8 KB
    unsigned long long red[16];
    int   hist[NBINS];                   // 9.2 KB
    int   coarse[256];
    float m1[384];
    float env2[2][128];
    float sdx[64], sdy[64], sdz[64];
    int   snm[64], sidx[64];
    float ca[3];
    int   cnt_sel, cnt_cand, selN, binB, needN;
};

__device__ __forceinline__ float dist_rn(float cax, float cay, float caz,
                                         float px, float py, float pz) {
    float dx = __fsub_rn(cax, px), dy = __fsub_rn(cay, py), dz = __fsub_rn(caz, pz);
    float d2 = __fadd_rn(__fadd_rn(__fmul_rn(dx, dx), __fmul_rn(dy, dy)),
                         __fmul_rn(dz, dz));
    return __fsqrt_rn(__fadd_rn(d2, 1e-12f));
}

__global__ void __launch_bounds__(256) k_ball(
    float* __restrict__ envout, const float* __restrict__ pos,
    const float* __restrict__ posx, const float* __restrict__ posy,
    const float* __restrict__ posz,
    const int* __restrict__ aname, const int* __restrict__ ca_idx,
    const float* __restrict__ embw_g, const float* __restrict__ m1_g) {
    __shared__ BallSM s;
    int tid = threadIdx.x;
    int r = blockIdx.x;

    for (int i = tid; i < NBINS; i += 256) s.hist[i] = 0;
    for (int i = tid; i < 384; i += 256) s.m1[i] = m1_g[i];
    if (tid == 0) {
        s.cnt_sel = 0; s.cnt_cand = 0;
        int ci = ca_idx[r];
        s.ca[0] = pos[3 * ci]; s.ca[1] = pos[3 * ci + 1]; s.ca[2] = pos[3 * ci + 2];
    }
    __syncthreads();
    float cax = s.ca[0], cay = s.ca[1], caz = s.ca[2];

    // pass 1: rounded d + float-radix histogram (no per-atom storage)
    #pragma unroll 4
    for (int i = tid; i < A_TOT; i += 256) {
        float d = dist_rn(cax, cay, caz, posx[i], posy[i], posz[i]);
        if (d < 10.0f) atomicAdd(&s.hist[__float_as_uint(d) >> 19], 1);
    }
    __syncthreads();

    { // coarse partial sums (9 bins per thread; 256*9 = 2304 = NBINS)
        int acc = 0, b0 = tid * 9;
        #pragma unroll
        for (int j = 0; j < 9; j++) acc += s.hist[b0 + j];
        s.coarse[tid] = acc;
    }
    __syncthreads();

    if (tid == 0) {
        int T = 0;
        for (int i = 0; i < 256; i++) T += s.coarse[i];
        int sel = T < KNBR ? T : KNBR;
        s.selN = sel;
        if (sel == 0) { s.binB = -1; s.needN = 0; }
        else {
            int cum = 0, cb = 0;
            while (cum + s.coarse[cb] < sel) { cum += s.coarse[cb]; cb++; }
            int b = cb * 9;
            while (cum + s.hist[b] < sel) { cum += s.hist[b]; b++; }
            s.binB = b;
            s.needN = sel - cum;
        }
    }
    __syncthreads();
    int B = s.binB;

    // pass 2: recompute d, accept keys < boundary bin, collect boundary bin
    #pragma unroll 4
    for (int i = tid; i < A_TOT; i += 256) {
        float d = dist_rn(cax, cay, caz, posx[i], posy[i], posz[i]);
        if (d < 10.0f) {
            int k = (int)(__float_as_uint(d) >> 19);
            if (k < B) {
                int p = atomicAdd(&s.cnt_sel, 1);
                s.sidx[p] = i;
            } else if (k == B) {
                int p = atomicAdd(&s.cnt_cand, 1);
                if (p < CAND_CAP)
                    s.cand[p] = ((unsigned long long)__float_as_uint(d) << 32) | (unsigned)i;
            }
        }
    }
    __syncthreads();

    // exact selection of `need` smallest from boundary bin
    // key = (d_bits, idx): equal rounded d -> lower idx first (top_k stable)
    int need = s.needN;
    int cbase = s.cnt_sel;
    int nc = s.cnt_cand; if (nc > CAND_CAP) nc = CAND_CAP;
    for (int it = 0; it < need; it++) {
        unsigned long long mn = ~0ull;
        for (int j = tid; j < nc; j += 256) {
            unsigned long long v = s.cand[j];
            if (v < mn) mn = v;
        }
        #pragma unroll
        for (int o = 16; o; o >>= 1) {
            unsigned long long w = __shfl_xor_sync(0xffffffffu, mn, o);
            if (w < mn) mn = w;
        }
        if ((tid & 31) == 0) s.red[tid >> 5] = mn;
        __syncthreads();
        if (tid == 0) {
            unsigned long long m = ~0ull;
            for (int w = 0; w < 8; w++) if (s.red[w] < m) m = s.red[w];
            s.red[8] = m;
            int idx = (m == ~0ull) ? s.sidx[0] : (int)(m & 0xffffffffu);
            s.sidx[cbase + it] = idx;
        }
        __syncthreads();
        unsigned long long win = s.red[8];
        for (int j = tid; j < nc; j += 256)
            if (s.cand[j] == win) s.cand[j] = ~0ull;
        __syncthreads();
    }

    int sel = s.selN;
    if (tid < sel) {
        int i = s.sidx[tid];
        s.sdx[tid] = pos[3 * i] - cax;
        s.sdy[tid] = pos[3 * i + 1] - cay;
        s.sdz[tid] = pos[3 * i + 2] - caz;
        s.snm[tid] = aname[i];
    }
    __syncthreads();

    // h = relu(embw[name] + delta @ M1); env = max (embw from global, L2-hot)
    int g = tid >> 7, d = tid & 127;
    float acc = 0.f;
    for (int j = g; j < sel; j += 2) {
        float h = __ldg(embw_g + s.snm[j] * 128 + d);
        h = fmaf(s.sdx[j], s.m1[d],       h);
        h = fmaf(s.sdy[j], s.m1[128 + d], h);
        h = fmaf(s.sdz[j], s.m1[256 + d], h);
        acc = fmaxf(acc, fmaxf(h, 0.f));
    }
    s.env2[g][d] = acc;
    __syncthreads();
    if (tid < 128) envout[r * 128 + tid] = fmaxf(s.env2[0][tid], s.env2[1][tid]);
}

// ---------------- packed-f32x2 tiled SGEMM, broadcast-B design -------------
// C = [relu](A' @ B + bias); A row-major [M,K], B row-major [K,N].
// BNA: A' = relu(A*scale + shift) applied at the A-tile fill.
template <bool RELU, bool BNA>
__global__ void __launch_bounds__(256) k_gemm2(
    const float* __restrict__ A, int lda, const float* __restrict__ B, int ldb,
    const float* __restrict__ bias, float* __restrict__ C, int ldc, int K,
    const float* __restrict__ bnscale, const float* __restrict__ bnshift) {
    __shared__ __align__(16) unsigned int As32[32][132];
    __shared__ __align__(16) unsigned long long Bs2[32][66];

    int m0 = blockIdx.y * 128, n0 = blockIdx.x * 64;
    int tid = threadIdx.x;
    int lane = tid & 31, cg = tid >> 5;     // cg: column group 0..7

    unsigned long long acc[2][8];
    #pragma unroll
    for (int p = 0; p < 2; p++)
        #pragma unroll
        for (int j = 0; j < 8; j++) acc[p][j] = 0ull;

    for (int k0 = 0; k0 < K; k0 += 32) {
        // ---- fill A tile transposed: As32[k][row] = A[m0+row][k0+k] -------
        #pragma unroll
        for (int l = tid; l < 1024; l += 256) {      // 128 rows x 8 float4
            int row = l >> 3, kq = (l & 7) * 4;
            float4 v = *(const float4*)(A + (m0 + row) * lda + k0 + kq);
            if (BNA) {
                float4 sc = *(const float4*)(bnscale + k0 + kq);
                float4 sh = *(const float4*)(bnshift + k0 + kq);
                v.x = fmaxf(fmaf(v.x, sc.x, sh.x), 0.f);
                v.y = fmaxf(fmaf(v.y, sc.y, sh.y), 0.f);
                v.z = fmaxf(fmaf(v.z, sc.z, sh.z), 0.f);
                v.w = fmaxf(fmaf(v.w, sc.w, sh.w), 0.f);
            }
            As32[kq][row]     = __float_as_uint(v.x);
            As32[kq + 1][row] = __float_as_uint(v.y);
            As32[kq + 2][row] = __float_as_uint(v.z);
            As32[kq + 3][row] = __float_as_uint(v.w);
        }
        // ---- fill B tile, pre-broadcast into {b,b} u64 pairs --------------
        #pragma unroll
        for (int l = tid; l < 512; l += 256) {       // 32 k x 16 float4
            int k = l >> 4, c4 = (l & 15) * 4;
            float4 v = *(const float4*)(B + (k0 + k) * ldb + n0 + c4);
            Bs2[k][c4]     = pack_bcast(v.x);
            Bs2[k][c4 + 1] = pack_bcast(v.y);
            Bs2[k][c4 + 2] = pack_bcast(v.z);
            Bs2[k][c4 + 3] = pack_bcast(v.w);
        }
        __syncthreads();
        #pragma unroll
        for (int k = 0; k < 32; k++) {
            const unsigned long long* ak = (const unsigned long long*)&As32[k][0];
            unsigned long long a0 = ak[lane];        // rows 2l, 2l+1
            unsigned long long a1 = ak[32 + lane];   // rows 64+2l, 65+2l
            const ulonglong2* bk = (const ulonglong2*)&Bs2[k][cg * 8];
            ulonglong2 b01 = bk[0], b23 = bk[1], b45 = bk[2], b67 = bk[3];
            unsigned long long b[8] = {b01.x, b01.y, b23.x, b23.y,
                                       b45.x, b45.y, b67.x, b67.y};
            #pragma unroll
            for (int j = 0; j < 8; j++) {
                FMA_F32X2(acc[0][j], a0, b[j], acc[0][j]);
                FMA_F32X2(acc[1][j], a1, b[j], acc[1][j]);
            }
        }
        __syncthreads();
    }

    // ---- epilogue: bias (+relu), write 4 rows x 8 cols per lane -----------
    float bb[8];
    *(float4*)&bb[0] = *(const float4*)(bias + n0 + cg * 8);
    *(float4*)&bb[4] = *(const float4*)(bias + n0 + cg * 8 + 4);
    #pragma unroll
    for (int p = 0; p < 2; p++) {
        float lo[8], hi[8];
        #pragma unroll
        for (int j = 0; j < 8; j++) {
            unpack2(acc[p][j], lo[j], hi[j]);
            lo[j] += bb[j]; hi[j] += bb[j];
            if (RELU) { lo[j] = fmaxf(lo[j], 0.f); hi[j] = fmaxf(hi[j], 0.f); }
        }
        int r0 = m0 + p * 64 + 2 * lane;
        float* c0 = C + r0 * ldc + n0 + cg * 8;
        float* c1 = c0 + ldc;
        *(float4*)c0       = *(float4*)&lo[0];
        *(float4*)(c0 + 4) = *(float4*)&lo[4];
        *(float4*)c1       = *(float4*)&hi[0];
        *(float4*)(c1 + 4) = *(float4*)&hi[4];
    }
}

// ---------------- BN stats -> folded scale/shift ---------------------------
__global__ void k_bnstats(const float* __restrict__ z, const float* __restrict__ gamma,
                          const float* __restrict__ beta, float* __restrict__ scale,
                          float* __restrict__ shift) {
    __shared__ float S[8][32], S2[8][32];
    int cx = threadIdx.x & 31, ry = threadIdx.x >> 5;
    int c = blockIdx.x * 32 + cx;
    float su = 0.f, sq = 0.f;
    for (int r = ry; r < R_TOT; r += 8) {
        float v = z[r * 512 + c];
        su += v; sq = fmaf(v, v, sq);
    }
    S[ry][cx] = su; S2[ry][cx] = sq;
    __syncthreads();
    if (threadIdx.x < 32) {
        int cc = blockIdx.x * 32 + threadIdx.x;
        float t = 0.f, t2 = 0.f;
        for (int i = 0; i < 8; i++) { t += S[i][threadIdx.x]; t2 += S2[i][threadIdx.x]; }
        float mean = t * (1.f / R_TOT);
        float var = t2 * (1.f / R_TOT) - mean * mean;
        float sc = gamma[cc] * rsqrtf(var + 1e-5f);
        scale[cc] = sc;
        shift[cc] = beta[cc] - mean * sc;
    }
}

// ---------------- launch ---------------------------------------------------
extern "C" void kernel_launch(void* const* d_in, const int* in_sizes, int n_in,
                              void* d_out, int out_size) {
    const float* node_feature = (const float*)d_in[0];
    const float* atom_pos     = (const float*)d_in[1];
    const int*   atom_name    = (const int*)d_in[2];
    const int*   ca_idx       = (const int*)d_in[3];
    const int*   edge_src     = (const int*)d_in[4];
    const int*   edge_dst     = (const int*)d_in[5];
    const int*   edge_rel     = (const int*)d_in[6];
    const float* emb_atom     = (const float*)d_in[7];
    const float* Wres         = (const float*)d_in[8];
    const float* bres         = (const float*)d_in[9];
    const float* Wxyz         = (const float*)d_in[10];
    const float* W1           = (const float*)d_in[11];
    const float* b1           = (const float*)d_in[12];
    const float* W2           = (const float*)d_in[13];
    const float* b2           = (const float*)d_in[14];
    const float* Wconv        = (const float*)d_in[15];
    const float* bconv        = (const float*)d_in[16];
    const float* Wself        = (const float*)d_in[17];
    const float* We1          = (const float*)d_in[18];
    const float* be1          = (const float*)d_in[19];
    const float* gamma1       = (const float*)d_in[20];
    const float* beta1        = (const float*)d_in[21];
    const float* We2          = (const float*)d_in[22];
    const float* be2          = (const float*)d_in[23];
    float* out = (float*)d_out;

    float* base = nullptr;
    cudaGetSymbolAddress((void**)&base, g_scratch);
    float* Xcat1 = base + OFF_XCAT1;
    float* Wcat  = base + OFF_WCAT;
    float* embw  = base + OFF_EMBW;
    float* m1    = base + OFF_M1;
    float* env   = base + OFF_ENV;
    float* Xcat2 = base + OFF_XCAT2;
    float* z     = base + OFF_Z;
    float* scale = base + OFF_SCALE;
    float* shift = base + OFF_SHIFT;
    float* posx  = base + OFF_POSX;
    float* posy  = base + OFF_POSY;
    float* posz  = base + OFF_POSZ;

    // setup (includes pos AoS->SoA transpose)
    k_prep<<<(267520 + A_TOT + 255) / 256, 256>>>(Wcat, embw, m1, posx, posy, posz,
                                                  Wconv, Wself, emb_atom, W1, b1, Wxyz,
                                                  atom_pos);
    k_resfeat<<<(R_TOT * 512) / 256, 256>>>(Xcat1, node_feature, Wres, bres);

    // relational scatter-sum
    k_scatter<<<E_TOT / 8, 256>>>(Xcat1, edge_src, edge_dst, edge_rel);

    // ball query + point MLP + maxpool (static smem, ~22 KB -> 8 blocks/SM)
    k_ball<<<R_TOT, 256>>>(env, atom_pos, posx, posy, posz,
                           atom_name, ca_idx, embw, m1);

    // env256 = relu(env128 @ W2 + b2) -> Xcat2[:,512:768]
    {
        dim3 grid(256 / 64, R_TOT / 128);
        k_gemm2<true, false><<<grid, 256>>>(env, 128, W2, 256, b2, Xcat2 + 512, 768, 128,
                                            nullptr, nullptr);
    }
    // hres = relu(Xcat1 @ Wcat + bconv) -> Xcat2[:,0:512]
    {
        dim3 grid(512 / 64, R_TOT / 128);
        k_gemm2<true, false><<<grid, 256>>>(Xcat1, 512, Wcat, 512, bconv, Xcat2, 768, 512,
                                            nullptr, nullptr);
    }
    // z = Xcat2 @ We1 + be1
    {
        dim3 grid(512 / 64, R_TOT / 128);
        k_gemm2<false, false><<<grid, 256>>>(Xcat2, 768, We1, 512, be1, z, 512, 768,
                                             nullptr, nullptr);
    }
    // BN stats -> folded affine
    k_bnstats<<<512 / 32, 256>>>(z, gamma1, beta1, scale, shift);
    // out = relu(BN(z)) @ We2 + be2
    {
        dim3 grid(512 / 64, R_TOT / 128);
        k_gemm2<false, true><<<grid, 256>>>(z, 512, We2, 512, be2, out, 512, 512,
                                            scale, shift);
    }
}

// round 12
// speedup vs baseline: 1.6023x; 1.1853x over previous
#include <cuda_runtime.h>

#define R_TOT 2048
#define A_TOT 16384
#define E_TOT 131072
#define KNBR  48
#define NBINS 2304          // d-bits >> 19 (exp + 4 mantissa bits); 256 thr x 9
#define CAND_CAP 1024

// ---------------- scratch (single __device__ blob, offsets in floats) ------
constexpr int OFF_XCAT1 = 0;
constexpr int OFF_WCAT  = OFF_XCAT1 + R_TOT * 512;   // 1048576
constexpr int OFF_EMBW  = OFF_WCAT  + 512 * 512;     // 1310720
constexpr int OFF_M1    = OFF_EMBW  + 39 * 128;      // 1315712
constexpr int OFF_ENV   = OFF_M1    + 384;           // 1316096
constexpr int OFF_XCAT2 = OFF_ENV   + R_TOT * 128;   // 1578240
constexpr int OFF_Z     = OFF_XCAT2 + R_TOT * 768;   // 3151104
constexpr int OFF_SCALE = OFF_Z     + R_TOT * 512;   // 4199680
constexpr int OFF_SHIFT = OFF_SCALE + 512;
constexpr int OFF_POSX  = OFF_SHIFT + 512;           // SoA positions
constexpr int OFF_POSY  = OFF_POSX + A_TOT;
constexpr int OFF_POSZ  = OFF_POSY + A_TOT;
constexpr int OFF_BNPA  = OFF_POSZ + A_TOT;          // BN partial sums [8][512]
constexpr int OFF_BNPB  = OFF_BNPA + 8 * 512;        // BN partial sumsq [8][512]
constexpr int SCRATCH_N = OFF_BNPB + 8 * 512;

__device__ __align__(16) float g_scratch[SCRATCH_N];

// ---- packed fp32x2 helpers (Blackwell FFMA2 path; ptxas won't auto-fuse) --
#define FMA_F32X2(d, a, b, c) \
    asm("fma.rn.f32x2 %0, %1, %2, %3;" : "=l"(d) : "l"(a), "l"(b), "l"(c))
__device__ __forceinline__ unsigned long long pack_bcast(float v) {
    unsigned long long r;
    asm("mov.b64 %0, {%1, %1};" : "=l"(r) : "f"(v));
    return r;
}
__device__ __forceinline__ void unpack2(unsigned long long v, float& lo, float& hi) {
    asm("mov.b64 {%0, %1}, %2;" : "=f"(lo), "=f"(hi) : "l"(v));
}

// ---------------- setup: Wcat copy, embW1b, M1, pos AoS->SoA ---------------
__global__ void k_prep(float* __restrict__ Wcat, float* __restrict__ embw,
                       float* __restrict__ m1, float* __restrict__ posx,
                       float* __restrict__ posy, float* __restrict__ posz,
                       const float* __restrict__ Wconv, const float* __restrict__ Wself,
                       const float* __restrict__ emb, const float* __restrict__ W1,
                       const float* __restrict__ b1, const float* __restrict__ Wxyz,
                       const float* __restrict__ pos) {
    int i = blockIdx.x * 256 + threadIdx.x;
    if (i < 262144) {
        int r = i >> 9;
        Wcat[i] = (r < 448) ? Wconv[i] : Wself[i - 448 * 512];
    } else if (i < 262144 + 4992) {
        int j = i - 262144;
        int e = j >> 7, d = j & 127;
        float acc = b1[d];
        for (int k = 0; k < 64; k++) acc = fmaf(emb[e * 64 + k], W1[k * 128 + d], acc);
        embw[j] = acc;
    } else if (i < 267520) {
        int j = i - 267136;
        int rr = j >> 7, d = j & 127;
        float acc = 0.f;
        for (int k = 0; k < 64; k++) acc = fmaf(Wxyz[rr * 64 + k], W1[k * 128 + d], acc);
        m1[j] = acc;
    } else if (i < 267520 + A_TOT) {
        int j = i - 267520;
        posx[j] = pos[3 * j];
        posy[j] = pos[3 * j + 1];
        posz[j] = pos[3 * j + 2];
    }
}

// ---------------- res_feat into Xcat1 tail + zero agg region ---------------
__global__ void k_resfeat(float* __restrict__ Xcat1, const float* __restrict__ nf,
                          const float* __restrict__ Wres, const float* __restrict__ bres) {
    int i = blockIdx.x * 256 + threadIdx.x;
    int r = i >> 9, c = i & 511;
    if (c < 448) { Xcat1[i] = 0.f; return; }
    int f = c - 448;
    float acc = bres[f];
    for (int k = 0; k < 21; k++) acc = fmaf(nf[r * 21 + k], Wres[k * 64 + f], acc);
    Xcat1[i] = acc;
}

// ---------------- relational scatter-sum (warp per edge) ------------------
__global__ void k_scatter(float* __restrict__ Xcat1, const int* __restrict__ esrc,
                          const int* __restrict__ edst, const int* __restrict__ erel) {
    int e = blockIdx.x * 8 + (threadIdx.x >> 5);
    int lane = threadIdx.x & 31;
    int s = esrc[e], d = edst[e], rl = erel[e];
    const float* rf = Xcat1 + s * 512 + 448;
    float* out = Xcat1 + d * 512 + rl * 64;
    atomicAdd(out + lane,      rf[lane]);
    atomicAdd(out + lane + 32, rf[lane + 32]);
}

// ---------------- ball query + point MLP + max-pool ------------------------
// Membership: d2 < 100 AND sqrt_rn(d2+1e-12) < 10 (equivalent to the
// reference predicate by rn-sqrt monotonicity; prefilter skips the sqrt
// sequence for ~90% of atoms). Ordering key = ROUNDED d bits, ties by idx:
// reproduces the reference's top_k exactly.
// Pass 1: float4 position loads (thread t owns atoms 1024c + 4t + q) and a
// per-thread 64-bit member mask (bit c*4+q). Pass 2 visits only set bits.
struct BallSM {
    unsigned long long cand[CAND_CAP];   // 8 KB
    unsigned long long red[16];
    int   hist[NBINS];                   // 9.2 KB
    int   coarse[256];
    float m1[384];
    float env2[2][128];
    float sdx[64], sdy[64], sdz[64];
    int   snm[64], sidx[64];
    float ca[3];
    int   cnt_sel, cnt_cand, selN, binB, needN;
};

__global__ void __launch_bounds__(256) k_ball(
    float* __restrict__ envout, const float* __restrict__ pos,
    const float* __restrict__ posx, const float* __restrict__ posy,
    const float* __restrict__ posz,
    const int* __restrict__ aname, const int* __restrict__ ca_idx,
    const float* __restrict__ embw_g, const float* __restrict__ m1_g) {
    __shared__ BallSM s;
    int tid = threadIdx.x;
    int r = blockIdx.x;

    for (int i = tid; i < NBINS; i += 256) s.hist[i] = 0;
    for (int i = tid; i < 384; i += 256) s.m1[i] = m1_g[i];
    if (tid == 0) {
        s.cnt_sel = 0; s.cnt_cand = 0;
        int ci = ca_idx[r];
        s.ca[0] = pos[3 * ci]; s.ca[1] = pos[3 * ci + 1]; s.ca[2] = pos[3 * ci + 2];
    }
    __syncthreads();
    float cax = s.ca[0], cay = s.ca[1], caz = s.ca[2];

    // pass 1: vectorized d2 prefilter -> sqrt for ~10% -> histogram + mask
    unsigned long long mask = 0;
    #pragma unroll
    for (int c = 0; c < A_TOT / 1024; c++) {
        int ibase = 1024 * c + 4 * tid;
        float4 px = *(const float4*)(posx + ibase);
        float4 py = *(const float4*)(posy + ibase);
        float4 pz = *(const float4*)(posz + ibase);
        float qx[4] = {px.x, px.y, px.z, px.w};
        float qy[4] = {py.x, py.y, py.z, py.w};
        float qz[4] = {pz.x, pz.y, pz.z, pz.w};
        #pragma unroll
        for (int q = 0; q < 4; q++) {
            float dx = __fsub_rn(cax, qx[q]);
            float dy = __fsub_rn(cay, qy[q]);
            float dz = __fsub_rn(caz, qz[q]);
            float d2 = __fadd_rn(__fadd_rn(__fmul_rn(dx, dx), __fmul_rn(dy, dy)),
                                 __fmul_rn(dz, dz));
            if (d2 < 100.0f) {
                float d = __fsqrt_rn(__fadd_rn(d2, 1e-12f));
                if (d < 10.0f) {
                    atomicAdd(&s.hist[__float_as_uint(d) >> 19], 1);
                    mask |= 1ull << (c * 4 + q);
                }
            }
        }
    }
    __syncthreads();

    { // coarse partial sums (9 bins per thread; 256*9 = 2304 = NBINS)
        int acc = 0, b0 = tid * 9;
        #pragma unroll
        for (int j = 0; j < 9; j++) acc += s.hist[b0 + j];
        s.coarse[tid] = acc;
    }
    __syncthreads();

    if (tid == 0) {
        int T = 0;
        for (int i = 0; i < 256; i++) T += s.coarse[i];
        int sel = T < KNBR ? T : KNBR;
        s.selN = sel;
        if (sel == 0) { s.binB = -1; s.needN = 0; }
        else {
            int cum = 0, cb = 0;
            while (cum + s.coarse[cb] < sel) { cum += s.coarse[cb]; cb++; }
            int b = cb * 9;
            while (cum + s.hist[b] < sel) { cum += s.hist[b]; b++; }
            s.binB = b;
            s.needN = sel - cum;
        }
    }
    __syncthreads();
    int B = s.binB;

    // pass 2: only member atoms (set bits) -> recompute d, classify by bin
    {
        unsigned long long m = mask;
        while (m) {
            int j = __ffsll((long long)m) - 1;
            m &= m - 1;
            int i = 1024 * (j >> 2) + 4 * tid + (j & 3);
            float dx = __fsub_rn(cax, posx[i]);
            float dy = __fsub_rn(cay, posy[i]);
            float dz = __fsub_rn(caz, posz[i]);
            float d2 = __fadd_rn(__fadd_rn(__fmul_rn(dx, dx), __fmul_rn(dy, dy)),
                                 __fmul_rn(dz, dz));
            float d = __fsqrt_rn(__fadd_rn(d2, 1e-12f));
            int k = (int)(__float_as_uint(d) >> 19);
            if (k < B) {
                int p = atomicAdd(&s.cnt_sel, 1);
                s.sidx[p] = i;
            } else if (k == B) {
                int p = atomicAdd(&s.cnt_cand, 1);
                if (p < CAND_CAP)
                    s.cand[p] = ((unsigned long long)__float_as_uint(d) << 32) | (unsigned)i;
            }
        }
    }
    __syncthreads();

    // exact selection of `need` smallest from boundary bin
    // key = (d_bits, idx): equal rounded d -> lower idx first (top_k stable)
    int need = s.needN;
    int cbase = s.cnt_sel;
    int nc = s.cnt_cand; if (nc > CAND_CAP) nc = CAND_CAP;
    for (int it = 0; it < need; it++) {
        unsigned long long mn = ~0ull;
        for (int j = tid; j < nc; j += 256) {
            unsigned long long v = s.cand[j];
            if (v < mn) mn = v;
        }
        #pragma unroll
        for (int o = 16; o; o >>= 1) {
            unsigned long long w = __shfl_xor_sync(0xffffffffu, mn, o);
            if (w < mn) mn = w;
        }
        if ((tid & 31) == 0) s.red[tid >> 5] = mn;
        __syncthreads();
        if (tid == 0) {
            unsigned long long m = ~0ull;
            for (int w = 0; w < 8; w++) if (s.red[w] < m) m = s.red[w];
            s.red[8] = m;
            int idx = (m == ~0ull) ? s.sidx[0] : (int)(m & 0xffffffffu);
            s.sidx[cbase + it] = idx;
        }
        __syncthreads();
        unsigned long long win = s.red[8];
        for (int j = tid; j < nc; j += 256)
            if (s.cand[j] == win) s.cand[j] = ~0ull;
        __syncthreads();
    }

    int sel = s.selN;
    if (tid < sel) {
        int i = s.sidx[tid];
        s.sdx[tid] = pos[3 * i] - cax;
        s.sdy[tid] = pos[3 * i + 1] - cay;
        s.sdz[tid] = pos[3 * i + 2] - caz;
        s.snm[tid] = aname[i];
    }
    __syncthreads();

    // h = relu(embw[name] + delta @ M1); env = max (embw from global, L2-hot)
    int g = tid >> 7, d = tid & 127;
    float acc = 0.f;
    for (int j = g; j < sel; j += 2) {
        float h = __ldg(embw_g + s.snm[j] * 128 + d);
        h = fmaf(s.sdx[j], s.m1[d],       h);
        h = fmaf(s.sdy[j], s.m1[128 + d], h);
        h = fmaf(s.sdz[j], s.m1[256 + d], h);
        acc = fmaxf(acc, fmaxf(h, 0.f));
    }
    s.env2[g][d] = acc;
    __syncthreads();
    if (tid < 128) envout[r * 128 + tid] = fmaxf(s.env2[0][tid], s.env2[1][tid]);
}

// ---------------- packed-f32x2 tiled SGEMM, broadcast-B design -------------
// C = [relu](A' @ B + bias); A row-major [M,K], B row-major [K,N].
// BNA: A' = relu(A*scale + shift) applied at the A-tile fill.
template <bool RELU, bool BNA>
__global__ void __launch_bounds__(256) k_gemm2(
    const float* __restrict__ A, int lda, const float* __restrict__ B, int ldb,
    const float* __restrict__ bias, float* __restrict__ C, int ldc, int K,
    const float* __restrict__ bnscale, const float* __restrict__ bnshift) {
    __shared__ __align__(16) unsigned int As32[32][132];
    __shared__ __align__(16) unsigned long long Bs2[32][66];

    int m0 = blockIdx.y * 128, n0 = blockIdx.x * 64;
    int tid = threadIdx.x;
    int lane = tid & 31, cg = tid >> 5;     // cg: column group 0..7

    unsigned long long acc[2][8];
    #pragma unroll
    for (int p = 0; p < 2; p++)
        #pragma unroll
        for (int j = 0; j < 8; j++) acc[p][j] = 0ull;

    for (int k0 = 0; k0 < K; k0 += 32) {
        // ---- fill A tile transposed: As32[k][row] = A[m0+row][k0+k] -------
        #pragma unroll
        for (int l = tid; l < 1024; l += 256) {      // 128 rows x 8 float4
            int row = l >> 3, kq = (l & 7) * 4;
            float4 v = *(const float4*)(A + (m0 + row) * lda + k0 + kq);
            if (BNA) {
                float4 sc = *(const float4*)(bnscale + k0 + kq);
                float4 sh = *(const float4*)(bnshift + k0 + kq);
                v.x = fmaxf(fmaf(v.x, sc.x, sh.x), 0.f);
                v.y = fmaxf(fmaf(v.y, sc.y, sh.y), 0.f);
                v.z = fmaxf(fmaf(v.z, sc.z, sh.z), 0.f);
                v.w = fmaxf(fmaf(v.w, sc.w, sh.w), 0.f);
            }
            As32[kq][row]     = __float_as_uint(v.x);
            As32[kq + 1][row] = __float_as_uint(v.y);
            As32[kq + 2][row] = __float_as_uint(v.z);
            As32[kq + 3][row] = __float_as_uint(v.w);
        }
        // ---- fill B tile, pre-broadcast into {b,b} u64 pairs --------------
        #pragma unroll
        for (int l = tid; l < 512; l += 256) {       // 32 k x 16 float4
            int k = l >> 4, c4 = (l & 15) * 4;
            float4 v = *(const float4*)(B + (k0 + k) * ldb + n0 + c4);
            Bs2[k][c4]     = pack_bcast(v.x);
            Bs2[k][c4 + 1] = pack_bcast(v.y);
            Bs2[k][c4 + 2] = pack_bcast(v.z);
            Bs2[k][c4 + 3] = pack_bcast(v.w);
        }
        __syncthreads();
        #pragma unroll
        for (int k = 0; k < 32; k++) {
            const unsigned long long* ak = (const unsigned long long*)&As32[k][0];
            unsigned long long a0 = ak[lane];        // rows 2l, 2l+1
            unsigned long long a1 = ak[32 + lane];   // rows 64+2l, 65+2l
            const ulonglong2* bk = (const ulonglong2*)&Bs2[k][cg * 8];
            ulonglong2 b01 = bk[0], b23 = bk[1], b45 = bk[2], b67 = bk[3];
            unsigned long long b[8] = {b01.x, b01.y, b23.x, b23.y,
                                       b45.x, b45.y, b67.x, b67.y};
            #pragma unroll
            for (int j = 0; j < 8; j++) {
                FMA_F32X2(acc[0][j], a0, b[j], acc[0][j]);
                FMA_F32X2(acc[1][j], a1, b[j], acc[1][j]);
            }
        }
        __syncthreads();
    }

    // ---- epilogue: bias (+relu), write 4 rows x 8 cols per lane -----------
    float bb[8];
    *(float4*)&bb[0] = *(const float4*)(bias + n0 + cg * 8);
    *(float4*)&bb[4] = *(const float4*)(bias + n0 + cg * 8 + 4);
    #pragma unroll
    for (int p = 0; p < 2; p++) {
        float lo[8], hi[8];
        #pragma unroll
        for (int j = 0; j < 8; j++) {
            unpack2(acc[p][j], lo[j], hi[j]);
            lo[j] += bb[j]; hi[j] += bb[j];
            if (RELU) { lo[j] = fmaxf(lo[j], 0.f); hi[j] = fmaxf(hi[j], 0.f); }
        }
        int r0 = m0 + p * 64 + 2 * lane;
        float* c0 = C + r0 * ldc + n0 + cg * 8;
        float* c1 = c0 + ldc;
        *(float4*)c0       = *(float4*)&lo[0];
        *(float4*)(c0 + 4) = *(float4*)&lo[4];
        *(float4*)c1       = *(float4*)&hi[0];
        *(float4*)(c1 + 4) = *(float4*)&hi[4];
    }
}

// ---------------- BN stats phase 1: per-rowgroup partial sums --------------
// grid (16, 8): x = 32-col group, y = 256-row group. Deterministic (each
// block writes its own gpart slice; no atomics).
__global__ void k_bnsum(const float* __restrict__ z, float* __restrict__ gpa,
                        float* __restrict__ gpb) {
    __shared__ float S[8][33], S2[8][33];
    int cx = threadIdx.x & 31, ry = threadIdx.x >> 5;
    int c = blockIdx.x * 32 + cx;
    int r0 = blockIdx.y * 256;
    float su = 0.f, sq = 0.f;
    for (int r = r0 + ry; r < r0 + 256; r += 8) {
        float v = z[r * 512 + c];
        su += v; sq = fmaf(v, v, sq);
    }
    S[ry][cx] = su; S2[ry][cx] = sq;
    __syncthreads();
    if (threadIdx.x < 32) {
        int cc = blockIdx.x * 32 + threadIdx.x;
        float t = 0.f, t2 = 0.f;
        #pragma unroll
        for (int i = 0; i < 8; i++) { t += S[i][threadIdx.x]; t2 += S2[i][threadIdx.x]; }
        gpa[blockIdx.y * 512 + cc] = t;
        gpb[blockIdx.y * 512 + cc] = t2;
    }
}

// ---------------- BN stats phase 2: fold partials -> scale/shift -----------
__global__ void k_bnfold(const float* __restrict__ gpa, const float* __restrict__ gpb,
                         const float* __restrict__ gamma, const float* __restrict__ beta,
                         float* __restrict__ scale, float* __restrict__ shift) {
    int c = blockIdx.x * 256 + threadIdx.x;   // 0..511
    float t = 0.f, t2 = 0.f;
    #pragma unroll
    for (int g = 0; g < 8; g++) { t += gpa[g * 512 + c]; t2 += gpb[g * 512 + c]; }
    float mean = t * (1.f / R_TOT);
    float var = t2 * (1.f / R_TOT) - mean * mean;
    float sc = gamma[c] * rsqrtf(var + 1e-5f);
    scale[c] = sc;
    shift[c] = beta[c] - mean * sc;
}

// ---------------- launch ---------------------------------------------------
extern "C" void kernel_launch(void* const* d_in, const int* in_sizes, int n_in,
                              void* d_out, int out_size) {
    const float* node_feature = (const float*)d_in[0];
    const float* atom_pos     = (const float*)d_in[1];
    const int*   atom_name    = (const int*)d_in[2];
    const int*   ca_idx       = (const int*)d_in[3];
    const int*   edge_src     = (const int*)d_in[4];
    const int*   edge_dst     = (const int*)d_in[5];
    const int*   edge_rel     = (const int*)d_in[6];
    const float* emb_atom     = (const float*)d_in[7];
    const float* Wres         = (const float*)d_in[8];
    const float* bres         = (const float*)d_in[9];
    const float* Wxyz         = (const float*)d_in[10];
    const float* W1           = (const float*)d_in[11];
    const float* b1           = (const float*)d_in[12];
    const float* W2           = (const float*)d_in[13];
    const float* b2           = (const float*)d_in[14];
    const float* Wconv        = (const float*)d_in[15];
    const float* bconv        = (const float*)d_in[16];
    const float* Wself        = (const float*)d_in[17];
    const float* We1          = (const float*)d_in[18];
    const float* be1          = (const float*)d_in[19];
    const float* gamma1       = (const float*)d_in[20];
    const float* beta1        = (const float*)d_in[21];
    const float* We2          = (const float*)d_in[22];
    const float* be2          = (const float*)d_in[23];
    float* out = (float*)d_out;

    float* base = nullptr;
    cudaGetSymbolAddress((void**)&base, g_scratch);
    float* Xcat1 = base + OFF_XCAT1;
    float* Wcat  = base + OFF_WCAT;
    float* embw  = base + OFF_EMBW;
    float* m1    = base + OFF_M1;
    float* env   = base + OFF_ENV;
    float* Xcat2 = base + OFF_XCAT2;
    float* z     = base + OFF_Z;
    float* scale = base + OFF_SCALE;
    float* shift = base + OFF_SHIFT;
    float* posx  = base + OFF_POSX;
    float* posy  = base + OFF_POSY;
    float* posz  = base + OFF_POSZ;
    float* bnpa  = base + OFF_BNPA;
    float* bnpb  = base + OFF_BNPB;

    // setup (includes pos AoS->SoA transpose)
    k_prep<<<(267520 + A_TOT + 255) / 256, 256>>>(Wcat, embw, m1, posx, posy, posz,
                                                  Wconv, Wself, emb_atom, W1, b1, Wxyz,
                                                  atom_pos);
    k_resfeat<<<(R_TOT * 512) / 256, 256>>>(Xcat1, node_feature, Wres, bres);

    // relational scatter-sum
    k_scatter<<<E_TOT / 8, 256>>>(Xcat1, edge_src, edge_dst, edge_rel);

    // ball query + point MLP + maxpool (static smem, ~22 KB -> 8 blocks/SM)
    k_ball<<<R_TOT, 256>>>(env, atom_pos, posx, posy, posz,
                           atom_name, ca_idx, embw, m1);

    // env256 = relu(env128 @ W2 + b2) -> Xcat2[:,512:768]
    {
        dim3 grid(256 / 64, R_TOT / 128);
        k_gemm2<true, false><<<grid, 256>>>(env, 128, W2, 256, b2, Xcat2 + 512, 768, 128,
                                            nullptr, nullptr);
    }
    // hres = relu(Xcat1 @ Wcat + bconv) -> Xcat2[:,0:512]
    {
        dim3 grid(512 / 64, R_TOT / 128);
        k_gemm2<true, false><<<grid, 256>>>(Xcat1, 512, Wcat, 512, bconv, Xcat2, 768, 512,
                                            nullptr, nullptr);
    }
    // z = Xcat2 @ We1 + be1
    {
        dim3 grid(512 / 64, R_TOT / 128);
        k_gemm2<false, false><<<grid, 256>>>(Xcat2, 768, We1, 512, be1, z, 512, 768,
                                             nullptr, nullptr);
    }
    // BN stats (2-phase, 128-block parallel) -> folded affine
    {
        dim3 grid(16, 8);
        k_bnsum<<<grid, 256>>>(z, bnpa, bnpb);
        k_bnfold<<<2, 256>>>(bnpa, bnpb, gamma1, beta1, scale, shift);
    }
    // out = relu(BN(z)) @ We2 + be2
    {
        dim3 grid(512 / 64, R_TOT / 128);
        k_gemm2<false, true><<<grid, 256>>>(z, 512, We2, 512, be2, out, 512, 512,
                                            scale, shift);
    }
}